// round 14
// baseline (speedup 1.0000x reference)
#include <cuda_runtime.h>
#include <cstdint>

#define NB 16
#define TT 128
#define VV 64
#define FF 16
#define TBL 8                    // timesteps per CTA
#define NTB (TT / TBL)           // 16 t-blocks (= slices)
#define NK 32                    // k-offsets (pairs (i, i+k), k=1..32)
#define PADF 20                  // padded feature stride (80B, 16B-aligned)
#define TSTRIDE (VV * PADF * 4)  // 5120 B per timestep plane

// scratch[slice][n][k-1][i]  (16*16*32*64 floats = 2 MB)
__device__ __align__(16) float g_part[NTB * NB * NK * VV];
// arrival counters per n (zero-init; finalizer resets -> graph-replay safe)
__device__ int g_cnt[NB];

__device__ __forceinline__ int prow(int r) {      // parity swizzle
    r &= 63;
    return (r >> 1) + ((r & 1) << 5);
}

__device__ __forceinline__ uint32_t smem_u32(const void* p) {
    uint32_t a;
    asm("{ .reg .u64 t; cvta.to.shared.u64 t, %1; cvt.u32.u64 %0, t; }"
        : "=r"(a) : "l"(p));
    return a;
}

// 16B shared load at immediate offset, directly into two u64 regs.
#define LDS2(LO, HI, AD, OFF)                                              \
    asm("ld.shared.v2.u64 {%0,%1}, [%2+" OFF "];"                          \
        : "=l"(LO), "=l"(HI) : "r"(AD))

// Load one 64B feature row (8 packed f32x2) from smem address AD.
#define LDROW(J, AD)                                                       \
    LDS2((J)[0], (J)[1], AD, "0");  LDS2((J)[2], (J)[3], AD, "16");        \
    LDS2((J)[4], (J)[5], AD, "32"); LDS2((J)[6], (J)[7], AD, "48")

// acc += af * |zi - zj|   (packed f32x2; abs = clear both sign bits)
__device__ __forceinline__ void step(uint64_t& acc, uint64_t zi, uint64_t zj,
                                     uint64_t af) {
    uint64_t d;
    asm("sub.rn.f32x2 %0, %1, %2;" : "=l"(d) : "l"(zi), "l"(zj));
    d &= 0x7FFFFFFF7FFFFFFFULL;
    asm("fma.rn.f32x2 %0, %1, %2, %3;"
        : "=l"(acc) : "l"(af), "l"(d), "l"(acc));
}

__device__ __forceinline__ void group(uint64_t& acc, const uint64_t* zi,
                                      const uint64_t* zj, const uint64_t* af) {
#pragma unroll
    for (int p = 0; p < 8; p++) step(acc, zi[p], zj[p], af[p]);
}

// ---------------------------------------------------------------------------
// Fused kernel, 24-warps/SM edition. 256 thr = 128 pair-threads x 2 t-slots
// (4 timesteps each); thread owns i-rows {i0,i0+1} x k in (k0,k0+8].
// Grid 16x16 = 256 CTAs at 3 CTAs/SM (40KB smem, <=85 regs) -> one wave.
// Tight-codegen inner loop from R13 (sub2, pipelined j-loads, immediate-
// offset v2.u64 LDS). Last CTA per n (atomic counter) finalizes.
// ---------------------------------------------------------------------------
__global__ __launch_bounds__(256, 3) void gl_fused_kernel(
    const float* __restrict__ x, const float* __restrict__ a,
    float* __restrict__ out)
{
    __shared__ __align__(16) float tile[TBL * VV * PADF];   // 40 KB (reused)
    __shared__ int isLast;

    const int n   = blockIdx.y;
    const int tb  = blockIdx.x;
    const int tid = threadIdx.x;
    const int q    = tid & 127;       // pair-thread id
    const int slot = tid >> 7;        // t-slot 0/1
    const int i0   = (q & 31) * 2;    // even base vertex
    const int k0   = (q >> 5) * 8;    // k-group base (0,8,16,24)

    // Load tile: x[n, tb*8 : +8, :, :] contiguous (8192 floats).
    const float4* src = (const float4*)(x + (size_t)(n * TT + tb * TBL) * VV * FF);
#pragma unroll
    for (int w = tid; w < TBL * VV * 4; w += 256) {
        float4 v = src[w];
        int t  = w >> 8;
        int r  = w & 255;
        int vv = r >> 2;
        int f4 = r & 3;
        *(float4*)&tile[((size_t)t * VV + prow(vv)) * PADF + f4 * 4] = v;
    }

    // Pack a[f] pairs into f32x2 regs (low 32 bits = even f).
    uint64_t af2[8];
#pragma unroll
    for (int k = 0; k < 8; k++) {
        af2[k] = (uint64_t)__float_as_uint(__ldg(&a[2 * k])) |
                 ((uint64_t)__float_as_uint(__ldg(&a[2 * k + 1])) << 32);
    }
    __syncthreads();

    // Precompute smem byte offsets (loop-invariant across t).
    const uint32_t tbase = smem_u32(tile);
    const uint32_t offI0 = (uint32_t)((i0 >> 1) * PADF) * 4;
    const uint32_t offI1 = (uint32_t)(((i0 >> 1) + 32) * PADF) * 4;
    uint32_t offJ[9];
#pragma unroll
    for (int r = 0; r < 9; r++)
        offJ[r] = (uint32_t)(prow(i0 + k0 + r + 1) * PADF) * 4;

    uint64_t accA[8], accB[8];
#pragma unroll
    for (int d = 0; d < 8; d++) { accA[d] = 0ull; accB[d] = 0ull; }

#pragma unroll 1
    for (int tt = 0; tt < 4; tt++) {
        const uint32_t base = tbase + (uint32_t)(slot * 4 + tt) * TSTRIDE;

        // i-rows (no negation needed with sub2).
        uint64_t zi0[8], zi1[8];
        LDROW(zi0, base + offI0);
        LDROW(zi1, base + offI1);

        // Software-pipelined j-rows: prefetch r+1 before computing r.
        uint64_t jb[2][8];
        LDROW(jb[0], base + offJ[0]);
#pragma unroll
        for (int r = 1; r <= 9; r++) {
            const int cur = (r - 1) & 1;
            const int nxt = r & 1;
            if (r < 9) { LDROW(jb[nxt], base + offJ[r]); }
            if (r <= 8) group(accA[r - 1], zi0, jb[cur], af2);
            if (r >= 2) group(accB[r - 2], zi1, jb[cur], af2);
        }
    }

    // Reduce packed halves to scalar.
    float sA[8], sB[8];
#pragma unroll
    for (int d = 0; d < 8; d++) {
        sA[d] = __uint_as_float((unsigned)accA[d]) +
                __uint_as_float((unsigned)(accA[d] >> 32));
        sB[d] = __uint_as_float((unsigned)accB[d]) +
                __uint_as_float((unsigned)(accB[d] >> 32));
    }

    // Combine the 2 t-slots in (reused) smem: slot 1 writes, slot 0 sums.
    __syncthreads();
    float* red = tile;                // 128 x 16 floats = 8 KB
    if (slot == 1) {
#pragma unroll
        for (int d = 0; d < 8; d++) {
            red[(q * 2 + 0) * 8 + d] = sA[d];
            red[(q * 2 + 1) * 8 + d] = sB[d];
        }
    }
    __syncthreads();
    if (slot == 0) {
        float* outp = &g_part[(((size_t)tb * NB + n) * NK + k0) * VV + i0];
#pragma unroll
        for (int d = 0; d < 8; d++) {
            float2 w;
            w.x = sA[d] + red[(q * 2 + 0) * 8 + d];
            w.y = sB[d] + red[(q * 2 + 1) * 8 + d];
            *(float2*)(outp + (size_t)d * VV) = w;    // [k-1][i0..i0+1]
        }
    }

    // ---- Last-block finalize for this n ----
    __threadfence();
    __syncthreads();
    if (tid == 0) {
        int old = atomicAdd(&g_cnt[n], 1);
        isLast = (old == NTB - 1);
    }
    __syncthreads();
    if (!isLast) return;

    float (*E)[VV + 2] = (float (*)[VV + 2])tile;     // reuse smem (16.9 KB)
    float* cinv = tile + VV * (VV + 2);

    {   // Phase A: reduce 16 slices at 2 positions/thread (batched MLP-8).
        const float4* g4 = (const float4*)g_part;
        const int ss   = NB * NK * VV / 4;            // 8192 float4 / slice
        const int base = n * (NK * VV / 4);           // n*512
        float4 s0 = make_float4(0.f, 0.f, 0.f, 0.f);
        float4 s1 = make_float4(0.f, 0.f, 0.f, 0.f);
#pragma unroll
        for (int sl = 0; sl < NTB; sl += 4) {
            float4 a0 = g4[(size_t)(sl + 0) * ss + base + tid];
            float4 a1 = g4[(size_t)(sl + 1) * ss + base + tid];
            float4 a2 = g4[(size_t)(sl + 2) * ss + base + tid];
            float4 a3 = g4[(size_t)(sl + 3) * ss + base + tid];
            float4 b0 = g4[(size_t)(sl + 0) * ss + base + 256 + tid];
            float4 b1 = g4[(size_t)(sl + 1) * ss + base + 256 + tid];
            float4 b2 = g4[(size_t)(sl + 2) * ss + base + 256 + tid];
            float4 b3 = g4[(size_t)(sl + 3) * ss + base + 256 + tid];
            s0.x += (a0.x + a1.x) + (a2.x + a3.x);
            s0.y += (a0.y + a1.y) + (a2.y + a3.y);
            s0.z += (a0.z + a1.z) + (a2.z + a3.z);
            s0.w += (a0.w + a1.w) + (a2.w + a3.w);
            s1.x += (b0.x + b1.x) + (b2.x + b3.x);
            s1.y += (b0.y + b1.y) + (b2.y + b3.y);
            s1.z += (b0.z + b1.z) + (b2.z + b3.z);
            s1.w += (b0.w + b1.w) + (b2.w + b3.w);
        }
        const float inv = 1.0f / (float)TT;
        float4 sv[2] = {s0, s1};
#pragma unroll
        for (int b = 0; b < 2; b++) {
            int pos   = tid + b * 256;
            int k_act = (pos >> 4) + 1;               // k (1..32)
            int ia    = (pos & 15) * 4;
            float ev[4] = { expf(fmaxf(sv[b].x * inv, 0.f)),
                            expf(fmaxf(sv[b].y * inv, 0.f)),
                            expf(fmaxf(sv[b].z * inv, 0.f)),
                            expf(fmaxf(sv[b].w * inv, 0.f)) };
#pragma unroll
            for (int p = 0; p < 4; p++) {
                int ii = ia + p;
                int jj = (ii + k_act) & 63;
                E[ii][jj] = ev[p];
                E[jj][ii] = ev[p];
            }
        }
        if (tid < VV) E[tid][tid] = 1.0f;             // diag: exp(relu(0))
    }
    __syncthreads();

    {   // Phase B: column sums over i (8 warps x 8 columns each).
        const int w = tid >> 5, lane = tid & 31;
#pragma unroll
        for (int c = 0; c < 8; c++) {
            int j = w * 8 + c;
            float v = E[lane][j] + E[lane + 32][j];
#pragma unroll
            for (int o = 16; o; o >>= 1) v += __shfl_xor_sync(0xffffffffu, v, o);
            if (lane == 0) cinv[j] = 1.0f / v;
        }
    }
    __syncthreads();

    {   // Phase C: out[n][i][jb..jb+15] = E[i][.] * cinv[.], 4x float4.
        const int i  = tid >> 2;
        const int jb = (tid & 3) * 16;
        float* o = out + (size_t)n * VV * VV + i * VV + jb;
#pragma unroll
        for (int g = 0; g < 4; g++) {
            float4 w;
            w.x = E[i][jb + g * 4 + 0] * cinv[jb + g * 4 + 0];
            w.y = E[i][jb + g * 4 + 1] * cinv[jb + g * 4 + 1];
            w.z = E[i][jb + g * 4 + 2] * cinv[jb + g * 4 + 2];
            w.w = E[i][jb + g * 4 + 3] * cinv[jb + g * 4 + 3];
            *(float4*)(o + g * 4) = w;
        }
    }

    if (tid == 0) g_cnt[n] = 0;       // reset for next graph replay
}

extern "C" void kernel_launch(void* const* d_in, const int* in_sizes, int n_in,
                              void* d_out, int out_size)
{
    const float* x = (const float*)d_in[0];       // [16,128,64,16] fp32
    const float* a = (const float*)d_in[1];       // [16,1] fp32
    float* out = (float*)d_out;                   // [16,64,64] fp32

    gl_fused_kernel<<<dim3(NTB, NB), 256>>>(x, a, out);
}